// round 13
// baseline (speedup 1.0000x reference)
#include <cuda_runtime.h>
#include <cuda_fp16.h>
#include <math.h>
#include <stdint.h>

#define BATCH 8
#define SEQ 1600
#define IN_DIM 256
#define DMODEL 512
#define NHEAD 8
#define HDIM 64
#define NJOINT 25
#define BH (BATCH*NHEAD)                 // 64
#define OUT_ELEMS (BATCH*SEQ*DMODEL)     // 6,553,600
#define PATT_ELEMS ((size_t)BH*SEQ*SEQ)  // 163,840,000

// scratch (__device__ globals; no allocation allowed)
__device__ __half g_q16[BH*SEQ*HDIM];
__device__ __half g_k16[BH*SEQ*HDIM];
__device__ __half g_vt16[BH*HDIM*SEQ];   // transposed: [bh][d][s]
__device__ float g_scores_fallback[PATT_ELEMS];

#define SW(o) ((o) ^ (((o) >> 3) & 0x70))
// exp(s/8) == ex2(s * 0.125 * log2(e))
#define EXPC 0.18033688011119247f

__device__ __forceinline__ uint32_t smem_u32(const void* p) {
    uint32_t a;
    asm("{ .reg .u64 t; cvta.to.shared.u64 t, %1; cvt.u32.u64 %0, t; }" : "=r"(a) : "l"(p));
    return a;
}
__device__ __forceinline__ float ex2f(float x) {
    float r; asm("ex2.approx.ftz.f32 %0, %1;" : "=f"(r) : "f"(x)); return r;
}
__device__ __forceinline__ void ldsm4(uint32_t* r, uint32_t addr) {
    asm volatile("ldmatrix.sync.aligned.m8n8.x4.shared.b16 {%0,%1,%2,%3}, [%4];"
                 : "=r"(r[0]), "=r"(r[1]), "=r"(r[2]), "=r"(r[3]) : "r"(addr));
}
__device__ __forceinline__ void mma16816(float* c, const uint32_t* a, const uint32_t* b) {
    asm volatile("mma.sync.aligned.m16n8k16.row.col.f32.f16.f16.f32 "
                 "{%0,%1,%2,%3}, {%4,%5,%6,%7}, {%8,%9}, {%0,%1,%2,%3};"
                 : "+f"(c[0]), "+f"(c[1]), "+f"(c[2]), "+f"(c[3])
                 : "r"(a[0]), "r"(a[1]), "r"(a[2]), "r"(a[3]), "r"(b[0]), "r"(b[1]));
}
__device__ __forceinline__ void cpasync16(uint32_t dst, const void* src) {
    asm volatile("cp.async.cg.shared.global [%0], [%1], 16;" :: "r"(dst), "l"(src));
}
__device__ __forceinline__ void cp_commit() { asm volatile("cp.async.commit_group;"); }
__device__ __forceinline__ void cp_wait1() { asm volatile("cp.async.wait_group 1;"); }
__device__ __forceinline__ void cp_wait0() { asm volatile("cp.async.wait_group 0;"); }
__device__ __forceinline__ void sts32(uint32_t addr, uint32_t v) {
    asm volatile("st.shared.u32 [%0], %1;" :: "r"(addr), "r"(v) : "memory");
}
__device__ __forceinline__ void stg_cs4(float* p, float a, float b, float c, float d) {
    asm volatile("st.global.cs.v4.f32 [%0], {%1, %2, %3, %4};"
                 :: "l"(p), "f"(a), "f"(b), "f"(c), "f"(d) : "memory");
}

// ---------------------------------------------------------------------------
// K1: QKV projection — all three via split-fp16 HMMA (3 terms). (unchanged)
//  z=0,1 (Q,K): direct [bh,s,d] epilogue.
//  z=2   (V):   ReLU + smem-transpose epilogue -> [bh,d,s], coalesced.
// ---------------------------------------------------------------------------
#define QKV_SMEM_BYTES 33792

__global__ __launch_bounds__(256, 2) void qkv_kernel(
    const float* __restrict__ x,
    const float* __restrict__ wq, const float* __restrict__ bq,
    const float* __restrict__ wk, const float* __restrict__ bk,
    const float* __restrict__ wv, const float* __restrict__ bv)
{
    __shared__ __align__(16) char smraw[QKV_SMEM_BYTES];
    const int z = blockIdx.z;
    const int t = threadIdx.x;

    __half* xh = (__half*)smraw;
    __half* xl = (__half*)(smraw + 6144);
    __half* wh = (__half*)(smraw + 12288);
    __half* wl = (__half*)(smraw + 18432);

    const float* W    = (z == 0) ? wq : (z == 1) ? wk : wv;
    const float* bias = (z == 0) ? bq : (z == 1) ? bk : bv;

    const int w = t >> 5, lane = t & 31;
    const int rowBase = blockIdx.y * 128;
    const int nBase   = blockIdx.x * 128;

    const uint32_t xh_b = smem_u32(xh), xl_b = smem_u32(xl);
    const uint32_t wh_b = smem_u32(wh), wl_b = smem_u32(wl);

    const int ar  = (lane & 7) + ((lane >> 3) & 1) * 8;
    const int akb = (lane >> 4) * 16;
    const uint32_t aoff = (uint32_t)((w * 16 + ar) * 48 + akb);
    const int bn  = (lane & 7) + ((lane >> 4) & 1) * 8;
    const int bkb = ((lane >> 3) & 1) * 16;
    uint32_t boff[8];
    #pragma unroll
    for (int jp = 0; jp < 8; jp++) boff[jp] = (uint32_t)((jp * 16 + bn) * 48 + bkb);

    float oc[16][4];
    #pragma unroll
    for (int j = 0; j < 16; j++) { oc[j][0]=0.f; oc[j][1]=0.f; oc[j][2]=0.f; oc[j][3]=0.f; }

    float4 xv[2]; float wvv[2][4];
    int xrow[2], xseg[2], wcol[2], wk4[2];
    #pragma unroll
    for (int p = 0; p < 2; p++) {
        int idx = t + p * 256;
        xrow[p] = idx >> 2; xseg[p] = idx & 3;
        wcol[p] = idx & 127; wk4[p] = (idx >> 7) * 4;
    }

    #pragma unroll
    for (int p = 0; p < 2; p++) {
        xv[p] = *(const float4*)&x[(size_t)(rowBase + xrow[p]) * IN_DIM + xseg[p] * 4];
        #pragma unroll
        for (int i = 0; i < 4; i++)
            wvv[p][i] = W[(size_t)(wk4[p] + i) * DMODEL + nBase + wcol[p]];
    }

    #pragma unroll 1
    for (int kc = 0; kc < 16; kc++) {
        __syncthreads();
        #pragma unroll
        for (int p = 0; p < 2; p++) {
            float vv[4] = {xv[p].x, xv[p].y, xv[p].z, xv[p].w};
            __align__(8) __half hs[4], ls[4];
            #pragma unroll
            for (int i = 0; i < 4; i++) {
                hs[i] = __float2half_rn(vv[i]);
                ls[i] = __float2half_rn(vv[i] - __half2float(hs[i]));
            }
            *(uint2*)&xh[xrow[p] * 24 + xseg[p] * 4] = *(uint2*)hs;
            *(uint2*)&xl[xrow[p] * 24 + xseg[p] * 4] = *(uint2*)ls;
            __align__(8) __half whs[4], wls[4];
            #pragma unroll
            for (int i = 0; i < 4; i++) {
                whs[i] = __float2half_rn(wvv[p][i]);
                wls[i] = __float2half_rn(wvv[p][i] - __half2float(whs[i]));
            }
            *(uint2*)&wh[wcol[p] * 24 + wk4[p]] = *(uint2*)whs;
            *(uint2*)&wl[wcol[p] * 24 + wk4[p]] = *(uint2*)wls;
        }
        __syncthreads();

        if (kc + 1 < 16) {
            const int k0n = (kc + 1) * 16;
            #pragma unroll
            for (int p = 0; p < 2; p++) {
                xv[p] = *(const float4*)&x[(size_t)(rowBase + xrow[p]) * IN_DIM + k0n + xseg[p] * 4];
                #pragma unroll
                for (int i = 0; i < 4; i++)
                    wvv[p][i] = W[(size_t)(k0n + wk4[p] + i) * DMODEL + nBase + wcol[p]];
            }
        }

        uint32_t ah[4], al[4];
        ldsm4(ah, xh_b + aoff);
        ldsm4(al, xl_b + aoff);
        #pragma unroll
        for (int jp = 0; jp < 8; jp++) {
            uint32_t bh4[4], bl4[4];
            ldsm4(bh4, wh_b + boff[jp]);
            ldsm4(bl4, wl_b + boff[jp]);
            mma16816(oc[2*jp],     ah, bh4);
            mma16816(oc[2*jp + 1], ah, bh4 + 2);
            mma16816(oc[2*jp],     ah, bl4);
            mma16816(oc[2*jp + 1], ah, bl4 + 2);
            mma16816(oc[2*jp],     al, bh4);
            mma16816(oc[2*jp + 1], al, bh4 + 2);
        }
    }

    const int c2 = (lane & 3) * 2;

    if (z < 2) {
        __half* D = (z == 0) ? g_q16 : g_k16;
        const int row0 = rowBase + w * 16 + (lane >> 2);
        const int row1 = row0 + 8;
        const int b0_ = row0 / SEQ, s0 = row0 - b0_ * SEQ;
        const int b1_ = row1 / SEQ, s1 = row1 - b1_ * SEQ;
        #pragma unroll
        for (int j = 0; j < 16; j++) {
            int col = nBase + j * 8 + c2;
            int h = col >> 6, ch = col & 63;
            float bb0 = bias[col], bb1 = bias[col + 1];
            __half2 v0 = __floats2half2_rn(oc[j][0] + bb0, oc[j][1] + bb1);
            __half2 v1 = __floats2half2_rn(oc[j][2] + bb0, oc[j][3] + bb1);
            *(__half2*)&D[((size_t)(b0_ * NHEAD + h) * SEQ + s0) * HDIM + ch] = v0;
            *(__half2*)&D[((size_t)(b1_ * NHEAD + h) * SEQ + s1) * HDIM + ch] = v1;
        }
    } else {
        // V: ReLU + transpose via smem -> g_vt16[bh][d][s]
        __syncthreads();
        __half* T = (__half*)smraw;    // [128 rows][132 pitch] fp16
        const int r0l = w * 16 + (lane >> 2);
        const int r1l = r0l + 8;
        #pragma unroll
        for (int j = 0; j < 16; j++) {
            int col = j * 8 + c2;
            float bb0 = bias[nBase + col], bb1 = bias[nBase + col + 1];
            __half2 v0 = __floats2half2_rn(fmaxf(oc[j][0] + bb0, 0.f),
                                           fmaxf(oc[j][1] + bb1, 0.f));
            __half2 v1 = __floats2half2_rn(fmaxf(oc[j][2] + bb0, 0.f),
                                           fmaxf(oc[j][3] + bb1, 0.f));
            *(__half2*)&T[r0l * 132 + col] = v0;
            *(__half2*)&T[r1l * 132 + col] = v1;
        }
        __syncthreads();
        const int sl = lane * 4;
        const int grow = rowBase + sl;
        const int b_ = grow / SEQ, s_ = grow - b_ * SEQ;
        #pragma unroll
        for (int cj = 0; cj < 16; cj++) {
            int col = w * 16 + cj;
            int dcol = nBase + col;
            int h = dcol >> 6, ch = dcol & 63;
            __align__(8) __half v[4];
            #pragma unroll
            for (int i = 0; i < 4; i++) v[i] = T[(sl + i) * 132 + col];
            *(uint2*)&g_vt16[((size_t)(b_ * NHEAD + h) * HDIM + ch) * SEQ + s_] = *(uint2*)v;
        }
    }
}

// ---------------------------------------------------------------------------
// K2 fused: fp16 HMMA attention, two-phase, 3-stage cp.async ring, warp-uniform
// mask skip. Phase-B p stores: staged to warp-private smem (fp16), flushed one
// tile LATE as coalesced 128B st.global.cs.v4 rows (pipelined, latency hidden).
// Dynamic smem: [0,24K) K ring, [24K,48K) V ring, [48K,+36864) p stage x2.
// ---------------------------------------------------------------------------
#define STG_PITCH 72                           // halves per staged row
#define STG_WARP  (16 * STG_PITCH * 2)         // 2304 B per warp per buffer
#define STG_BUF   (8 * STG_WARP)               // 18432 B per buffer
#define ATTN_SMEM_BYTES (49152 + 2 * STG_BUF)  // 86016

__global__ __launch_bounds__(256, 2) void attn_kernel(
    float* __restrict__ Pext, int use_ext, float* __restrict__ out)
{
    extern __shared__ __align__(16) char dsm[];

    float* P = use_ext ? Pext : g_scores_fallback;
    const int tid = threadIdx.x, w = tid >> 5, lane = tid & 31;
    const int bh = blockIdx.y;
    const int qBase = blockIdx.x * 128;

    const int row0 = qBase + w * 16 + (lane >> 2);
    const int row1 = row0 + 8;
    const int c2   = (lane & 3) * 2;
    const int lo0 = (row0 / NJOINT) * NJOINT, hi0 = lo0 + NJOINT;
    const int lo1 = (row1 / NJOINT) * NJOINT, hi1 = lo1 + NJOINT;
    const int wrow = qBase + w * 16;
    const int loW = (wrow / NJOINT) * NJOINT;
    const int hiW = ((wrow + 15) / NJOINT) * NJOINT + NJOINT;

    const __half* q = g_q16 + (size_t)bh * SEQ * HDIM;
    const char* kB = (const char*)(g_k16 + (size_t)bh * SEQ * HDIM);
    const char* vB = (const char*)(g_vt16 + (size_t)bh * HDIM * SEQ);

    uint32_t qf[4][4];
    {
        int r0c = min(row0, SEQ - 1), r1c = min(row1, SEQ - 1);
        #pragma unroll
        for (int t = 0; t < 4; t++) {
            qf[t][0] = *(const uint32_t*)&q[(size_t)r0c * HDIM + t*16 + c2];
            qf[t][1] = *(const uint32_t*)&q[(size_t)r1c * HDIM + t*16 + c2];
            qf[t][2] = *(const uint32_t*)&q[(size_t)r0c * HDIM + t*16 + 8 + c2];
            qf[t][3] = *(const uint32_t*)&q[(size_t)r1c * HDIM + t*16 + 8 + c2];
        }
    }

    const uint32_t sk_b = smem_u32(dsm);
    const uint32_t sv_b = sk_b + 24576;
    const uint32_t st_base = sk_b + 49152;
    // staging write addresses (per thread): row = lane>>2, col byte = (j*8+c2)*2
    const uint32_t stgw = st_base + w * STG_WARP + ((lane >> 2) * STG_PITCH + c2) * 2;

    uint32_t dstoff[2]; uint32_t srcKoff[2], srcVoff[2];
    #pragma unroll
    for (int p = 0; p < 2; p++) {
        int i = tid + p * 256;
        int r = i >> 3, cb = (i & 7) * 16;
        dstoff[p]  = SW(r * 128 + cb);
        srcKoff[p] = r * 128 + cb;
        srcVoff[p] = r * (SEQ * 2) + cb;
    }
    const int lrow = lane & 7;
    const int lcb  = (lane >> 3) * 16;
    uint32_t lof[8];
    #pragma unroll
    for (int j = 0; j < 8; j++) lof[j] = SW((j * 8 + lrow) * 128 + lcb);

    float rsum0 = 0.f, rsum1 = 0.f;

    // ================= Phase A: rowsum only =================
    #pragma unroll
    for (int p = 0; p < 2; p++)
        cpasync16(sk_b + dstoff[p], kB + srcKoff[p]);
    cp_commit();

    int cur = 0;
    #pragma unroll 1
    for (int kt = 0; kt < 25; kt++) {
        const int k0 = kt * 64;
        const uint32_t cb_ = sk_b + cur * 8192;
        if (kt + 1 < 25) {
            int nxt = cur + 1; if (nxt == 3) nxt = 0;
            const uint32_t nb = sk_b + nxt * 8192;
            #pragma unroll
            for (int p = 0; p < 2; p++)
                cpasync16(nb + dstoff[p], kB + (kt + 1) * 8192 + srcKoff[p]);
            cp_commit();
            cp_wait1();
        } else cp_wait0();
        __syncthreads();

        const bool needMask = (k0 < hiW) && (k0 + 64 > loW);

        #pragma unroll
        for (int jp = 0; jp < 4; jp++) {
            uint32_t b0[8], b1[8];
            {
                uint32_t a = cb_ + lof[jp * 2];
                ldsm4(b0, a); ldsm4(b0 + 4, a ^ 64);
                uint32_t b = cb_ + lof[jp * 2 + 1];
                ldsm4(b1, b); ldsm4(b1 + 4, b ^ 64);
            }
            float c0[4] = {0.f,0.f,0.f,0.f}, c1[4] = {0.f,0.f,0.f,0.f};
            #pragma unroll
            for (int t = 0; t < 4; t++) {
                mma16816(c0, qf[t], b0 + 2*t);
                mma16816(c1, qf[t], b1 + 2*t);
            }
            if (needMask) {
                #pragma unroll
                for (int jj = 0; jj < 2; jj++) {
                    const float* cc = jj ? c1 : c0;
                    int ka = k0 + (jp * 2 + jj) * 8 + c2, kb2 = ka + 1;
                    bool a00 = (ka  < lo0) | (ka  >= hi0) | (ka  == row0);
                    bool a01 = (kb2 < lo0) | (kb2 >= hi0) | (kb2 == row0);
                    bool a10 = (ka  < lo1) | (ka  >= hi1) | (ka  == row1);
                    bool a11 = (kb2 < lo1) | (kb2 >= hi1) | (kb2 == row1);
                    rsum0 += (a00 ? ex2f(cc[0] * EXPC) : 0.f)
                           + (a01 ? ex2f(cc[1] * EXPC) : 0.f);
                    rsum1 += (a10 ? ex2f(cc[2] * EXPC) : 0.f)
                           + (a11 ? ex2f(cc[3] * EXPC) : 0.f);
                }
            } else {
                rsum0 += ex2f(c0[0] * EXPC) + ex2f(c0[1] * EXPC)
                       + ex2f(c1[0] * EXPC) + ex2f(c1[1] * EXPC);
                rsum1 += ex2f(c0[2] * EXPC) + ex2f(c0[3] * EXPC)
                       + ex2f(c1[2] * EXPC) + ex2f(c1[3] * EXPC);
            }
        }
        cur = cur + 1; if (cur == 3) cur = 0;
    }

    #pragma unroll
    for (int off = 1; off < 4; off <<= 1) {
        rsum0 += __shfl_xor_sync(0xffffffffu, rsum0, off);
        rsum1 += __shfl_xor_sync(0xffffffffu, rsum1, off);
    }
    const float inv0 = (row0 < SEQ) ? 1.f / rsum0 : 0.f;
    const float inv1 = (row1 < SEQ) ? 1.f / rsum1 : 0.f;

    float oc[8][4];
    #pragma unroll
    for (int j = 0; j < 8; j++) { oc[j][0]=0.f; oc[j][1]=0.f; oc[j][2]=0.f; oc[j][3]=0.f; }

    // phase-transition guard
    __syncthreads();

    // ================= Phase B: recompute, stage p, O += pV, flush late ======
    #pragma unroll
    for (int p = 0; p < 2; p++) {
        cpasync16(sk_b + dstoff[p], kB + srcKoff[p]);
        cpasync16(sv_b + dstoff[p], vB + srcVoff[p]);
    }
    cp_commit();

    // flush geometry (warp-collective, coalesced): 4 rows/pass, 128B per row
    const int fr  = lane >> 3;           // 0..3
    const int fcb = (lane & 7) * 16;     // 16B chunk within row
    const uint32_t fwb = st_base + w * STG_WARP;

    cur = 0;
    #pragma unroll 1
    for (int kt = 0; kt < 25; kt++) {
        const int k0 = kt * 64;
        const uint32_t ckb = sk_b + cur * 8192;
        const uint32_t cvb = sv_b + cur * 8192;
        if (kt + 1 < 25) {
            int nxt = cur + 1; if (nxt == 3) nxt = 0;
            #pragma unroll
            for (int p = 0; p < 2; p++) {
                cpasync16(sk_b + nxt * 8192 + dstoff[p], kB + (kt + 1) * 8192 + srcKoff[p]);
                cpasync16(sv_b + nxt * 8192 + dstoff[p], vB + (kt + 1) * 128  + srcVoff[p]);
            }
            cp_commit();
            cp_wait1();
        } else cp_wait0();
        __syncthreads();

        const bool needMask = (k0 < hiW) && (k0 + 64 > loW);
        const uint32_t stgcur = stgw + (kt & 1) * STG_BUF;

        uint32_t pa[4][4];
        #pragma unroll
        for (int jp = 0; jp < 4; jp++) {
            uint32_t b0[8], b1[8];
            {
                uint32_t a = ckb + lof[jp * 2];
                ldsm4(b0, a); ldsm4(b0 + 4, a ^ 64);
                uint32_t b = ckb + lof[jp * 2 + 1];
                ldsm4(b1, b); ldsm4(b1 + 4, b ^ 64);
            }
            float c0[4] = {0.f,0.f,0.f,0.f}, c1[4] = {0.f,0.f,0.f,0.f};
            #pragma unroll
            for (int t = 0; t < 4; t++) {
                mma16816(c0, qf[t], b0 + 2*t);
                mma16816(c1, qf[t], b1 + 2*t);
            }
            #pragma unroll
            for (int jj = 0; jj < 2; jj++) {
                const float* cc = jj ? c1 : c0;
                const int j = jp * 2 + jj;
                float p00, p01, p10, p11;
                if (needMask) {
                    int ka = k0 + j * 8 + c2, kb2 = ka + 1;
                    bool a00 = (ka  < lo0) | (ka  >= hi0) | (ka  == row0);
                    bool a01 = (kb2 < lo0) | (kb2 >= hi0) | (kb2 == row0);
                    bool a10 = (ka  < lo1) | (ka  >= hi1) | (ka  == row1);
                    bool a11 = (kb2 < lo1) | (kb2 >= hi1) | (kb2 == row1);
                    p00 = a00 ? ex2f(cc[0] * EXPC) * inv0 : 0.f;
                    p01 = a01 ? ex2f(cc[1] * EXPC) * inv0 : 0.f;
                    p10 = a10 ? ex2f(cc[2] * EXPC) * inv1 : 0.f;
                    p11 = a11 ? ex2f(cc[3] * EXPC) * inv1 : 0.f;
                } else {
                    p00 = ex2f(cc[0] * EXPC) * inv0;
                    p01 = ex2f(cc[1] * EXPC) * inv0;
                    p10 = ex2f(cc[2] * EXPC) * inv1;
                    p11 = ex2f(cc[3] * EXPC) * inv1;
                }
                __half2 h0 = __floats2half2_rn(p00, p01);
                __half2 h1 = __floats2half2_rn(p10, p11);
                pa[jp][jj * 2 + 0] = *(uint32_t*)&h0;
                pa[jp][jj * 2 + 1] = *(uint32_t*)&h1;
                sts32(stgcur + j * 16, *(uint32_t*)&h0);
                sts32(stgcur + 8 * STG_PITCH * 2 + j * 16, *(uint32_t*)&h1);
            }
        }

        #pragma unroll
        for (int jp = 0; jp < 4; jp++) {
            uint32_t b0[8], b1[8];
            {
                uint32_t a = cvb + lof[jp * 2];
                ldsm4(b0, a); ldsm4(b0 + 4, a ^ 64);
                uint32_t b = cvb + lof[jp * 2 + 1];
                ldsm4(b1, b); ldsm4(b1 + 4, b ^ 64);
            }
            #pragma unroll
            for (int t = 0; t < 4; t++) {
                mma16816(oc[jp * 2],     pa[t], b0 + 2*t);
                mma16816(oc[jp * 2 + 1], pa[t], b1 + 2*t);
            }
        }

        // ---- flush PREVIOUS tile's staged p (latency hidden by this tile) ----
        if (kt > 0 && wrow < SEQ) {
            const uint32_t fb = fwb + ((kt - 1) & 1) * STG_BUF;
            const int k0p = k0 - 64;
            #pragma unroll
            for (int it = 0; it < 4; it++) {
                int r = it * 4 + fr;
                uint32_t u0, u1, u2, u3;
                asm volatile("ld.shared.v4.u32 {%0,%1,%2,%3}, [%4];"
                             : "=r"(u0), "=r"(u1), "=r"(u2), "=r"(u3)
                             : "r"(fb + r * (STG_PITCH * 2) + fcb));
                float2 f0 = __half22float2(*(__half2*)&u0);
                float2 f1 = __half22float2(*(__half2*)&u1);
                float2 f2 = __half22float2(*(__half2*)&u2);
                float2 f3 = __half22float2(*(__half2*)&u3);
                float* dst = P + ((size_t)bh * SEQ + wrow + r) * SEQ + k0p + (lane & 7) * 8;
                stg_cs4(dst,     f0.x, f0.y, f1.x, f1.y);
                stg_cs4(dst + 4, f2.x, f2.y, f3.x, f3.y);
            }
        }
        cur = cur + 1; if (cur == 3) cur = 0;
    }

    // flush the final tile (kt=24, buffer 0)
    if (wrow < SEQ) {
        __syncwarp();
        const uint32_t fb = fwb + (24 & 1) * STG_BUF;
        #pragma unroll
        for (int it = 0; it < 4; it++) {
            int r = it * 4 + fr;
            uint32_t u0, u1, u2, u3;
            asm volatile("ld.shared.v4.u32 {%0,%1,%2,%3}, [%4];"
                         : "=r"(u0), "=r"(u1), "=r"(u2), "=r"(u3)
                         : "r"(fb + r * (STG_PITCH * 2) + fcb));
            float2 f0 = __half22float2(*(__half2*)&u0);
            float2 f1 = __half22float2(*(__half2*)&u1);
            float2 f2 = __half22float2(*(__half2*)&u2);
            float2 f3 = __half22float2(*(__half2*)&u3);
            float* dst = P + ((size_t)bh * SEQ + wrow + r) * SEQ + 24 * 64 + (lane & 7) * 8;
            stg_cs4(dst,     f0.x, f0.y, f1.x, f1.y);
            stg_cs4(dst + 4, f2.x, f2.y, f3.x, f3.y);
        }
    }

    const int b_ = bh >> 3, h_ = bh & 7;
    float* ob0 = out + ((size_t)b_ * SEQ + row0) * DMODEL + h_ * HDIM;
    float* ob1 = out + ((size_t)b_ * SEQ + row1) * DMODEL + h_ * HDIM;
    #pragma unroll
    for (int j = 0; j < 8; j++) {
        if (row0 < SEQ) *(float2*)&ob0[j * 8 + c2] = make_float2(oc[j][0], oc[j][1]);
        if (row1 < SEQ) *(float2*)&ob1[j * 8 + c2] = make_float2(oc[j][2], oc[j][3]);
    }
}

// ---------------------------------------------------------------------------
extern "C" void kernel_launch(void* const* d_in, const int* in_sizes, int n_in,
                              void* d_out, int out_size)
{
    const float* x  = (const float*)d_in[0];
    const float* wq = (const float*)d_in[1];
    const float* bq = (const float*)d_in[2];
    const float* wk = (const float*)d_in[3];
    const float* bk = (const float*)d_in[4];
    const float* wv = (const float*)d_in[5];
    const float* bv = (const float*)d_in[6];
    float* out = (float*)d_out;

    int use_ext = ((size_t)out_size >= OUT_ELEMS + PATT_ELEMS) ? 1 : 0;
    float* Pext = out + OUT_ELEMS;

    static int attr_set = 0;
    if (!attr_set) {
        cudaFuncSetAttribute(attn_kernel, cudaFuncAttributeMaxDynamicSharedMemorySize,
                             ATTN_SMEM_BYTES);
        attr_set = 1;
    }

    {   // K1: QKV -> fp16, all HMMA (V transposed via smem)
        dim3 grid(DMODEL / 128, (BATCH * SEQ) / 128, 3);
        qkv_kernel<<<grid, 256>>>(x, wq, bq, wk, bk, wv, bv);
    }
    {   // K2 fused: two-phase fp16 HMMA attention -> p (final) + out
        dim3 grid((SEQ + 127) / 128, BH);
        attn_kernel<<<grid, 256, ATTN_SMEM_BYTES>>>(Pext, use_ext, out);
    }
}

// round 14
// speedup vs baseline: 1.1469x; 1.1469x over previous
#include <cuda_runtime.h>
#include <cuda_fp16.h>
#include <math.h>
#include <stdint.h>

#define BATCH 8
#define SEQ 1600
#define IN_DIM 256
#define DMODEL 512
#define NHEAD 8
#define HDIM 64
#define NJOINT 25
#define BH (BATCH*NHEAD)                 // 64
#define OUT_ELEMS (BATCH*SEQ*DMODEL)     // 6,553,600
#define PATT_ELEMS ((size_t)BH*SEQ*SEQ)  // 163,840,000

// scratch (__device__ globals; no allocation allowed)
__device__ __half g_q16[BH*SEQ*HDIM];
__device__ __half g_k16[BH*SEQ*HDIM];
__device__ __half g_vt16[BH*HDIM*SEQ];   // transposed: [bh][d][s]
__device__ float g_scores_fallback[PATT_ELEMS];

#define SW(o) ((o) ^ (((o) >> 3) & 0x70))
// exp(s/8) == ex2(s * 0.125 * log2(e))
#define EXPC 0.18033688011119247f

__device__ __forceinline__ uint32_t smem_u32(const void* p) {
    uint32_t a;
    asm("{ .reg .u64 t; cvta.to.shared.u64 t, %1; cvt.u32.u64 %0, t; }" : "=r"(a) : "l"(p));
    return a;
}
__device__ __forceinline__ float ex2f(float x) {
    float r; asm("ex2.approx.ftz.f32 %0, %1;" : "=f"(r) : "f"(x)); return r;
}
__device__ __forceinline__ void ldsm4(uint32_t* r, uint32_t addr) {
    asm volatile("ldmatrix.sync.aligned.m8n8.x4.shared.b16 {%0,%1,%2,%3}, [%4];"
                 : "=r"(r[0]), "=r"(r[1]), "=r"(r[2]), "=r"(r[3]) : "r"(addr));
}
__device__ __forceinline__ void mma16816(float* c, const uint32_t* a, const uint32_t* b) {
    asm volatile("mma.sync.aligned.m16n8k16.row.col.f32.f16.f16.f32 "
                 "{%0,%1,%2,%3}, {%4,%5,%6,%7}, {%8,%9}, {%0,%1,%2,%3};"
                 : "+f"(c[0]), "+f"(c[1]), "+f"(c[2]), "+f"(c[3])
                 : "r"(a[0]), "r"(a[1]), "r"(a[2]), "r"(a[3]), "r"(b[0]), "r"(b[1]));
}
__device__ __forceinline__ void cpasync16(uint32_t dst, const void* src) {
    asm volatile("cp.async.cg.shared.global [%0], [%1], 16;" :: "r"(dst), "l"(src));
}
__device__ __forceinline__ void cp_commit() { asm volatile("cp.async.commit_group;"); }
__device__ __forceinline__ void cp_wait1() { asm volatile("cp.async.wait_group 1;"); }
__device__ __forceinline__ void cp_wait0() { asm volatile("cp.async.wait_group 0;"); }
__device__ __forceinline__ void stg_cs2(float* p, float a, float b) {
    asm volatile("st.global.cs.v2.f32 [%0], {%1, %2};" :: "l"(p), "f"(a), "f"(b) : "memory");
}

// ---------------------------------------------------------------------------
// K1: QKV projection — all three via split-fp16 HMMA (3 terms). (unchanged)
//  z=0,1 (Q,K): direct [bh,s,d] epilogue.
//  z=2   (V):   ReLU + smem-transpose epilogue -> [bh,d,s], coalesced.
// ---------------------------------------------------------------------------
#define QKV_SMEM_BYTES 33792

__global__ __launch_bounds__(256, 2) void qkv_kernel(
    const float* __restrict__ x,
    const float* __restrict__ wq, const float* __restrict__ bq,
    const float* __restrict__ wk, const float* __restrict__ bk,
    const float* __restrict__ wv, const float* __restrict__ bv)
{
    __shared__ __align__(16) char smraw[QKV_SMEM_BYTES];
    const int z = blockIdx.z;
    const int t = threadIdx.x;

    __half* xh = (__half*)smraw;
    __half* xl = (__half*)(smraw + 6144);
    __half* wh = (__half*)(smraw + 12288);
    __half* wl = (__half*)(smraw + 18432);

    const float* W    = (z == 0) ? wq : (z == 1) ? wk : wv;
    const float* bias = (z == 0) ? bq : (z == 1) ? bk : bv;

    const int w = t >> 5, lane = t & 31;
    const int rowBase = blockIdx.y * 128;
    const int nBase   = blockIdx.x * 128;

    const uint32_t xh_b = smem_u32(xh), xl_b = smem_u32(xl);
    const uint32_t wh_b = smem_u32(wh), wl_b = smem_u32(wl);

    const int ar  = (lane & 7) + ((lane >> 3) & 1) * 8;
    const int akb = (lane >> 4) * 16;
    const uint32_t aoff = (uint32_t)((w * 16 + ar) * 48 + akb);
    const int bn  = (lane & 7) + ((lane >> 4) & 1) * 8;
    const int bkb = ((lane >> 3) & 1) * 16;
    uint32_t boff[8];
    #pragma unroll
    for (int jp = 0; jp < 8; jp++) boff[jp] = (uint32_t)((jp * 16 + bn) * 48 + bkb);

    float oc[16][4];
    #pragma unroll
    for (int j = 0; j < 16; j++) { oc[j][0]=0.f; oc[j][1]=0.f; oc[j][2]=0.f; oc[j][3]=0.f; }

    float4 xv[2]; float wvv[2][4];
    int xrow[2], xseg[2], wcol[2], wk4[2];
    #pragma unroll
    for (int p = 0; p < 2; p++) {
        int idx = t + p * 256;
        xrow[p] = idx >> 2; xseg[p] = idx & 3;
        wcol[p] = idx & 127; wk4[p] = (idx >> 7) * 4;
    }

    #pragma unroll
    for (int p = 0; p < 2; p++) {
        xv[p] = *(const float4*)&x[(size_t)(rowBase + xrow[p]) * IN_DIM + xseg[p] * 4];
        #pragma unroll
        for (int i = 0; i < 4; i++)
            wvv[p][i] = W[(size_t)(wk4[p] + i) * DMODEL + nBase + wcol[p]];
    }

    #pragma unroll 1
    for (int kc = 0; kc < 16; kc++) {
        __syncthreads();
        #pragma unroll
        for (int p = 0; p < 2; p++) {
            float vv[4] = {xv[p].x, xv[p].y, xv[p].z, xv[p].w};
            __align__(8) __half hs[4], ls[4];
            #pragma unroll
            for (int i = 0; i < 4; i++) {
                hs[i] = __float2half_rn(vv[i]);
                ls[i] = __float2half_rn(vv[i] - __half2float(hs[i]));
            }
            *(uint2*)&xh[xrow[p] * 24 + xseg[p] * 4] = *(uint2*)hs;
            *(uint2*)&xl[xrow[p] * 24 + xseg[p] * 4] = *(uint2*)ls;
            __align__(8) __half whs[4], wls[4];
            #pragma unroll
            for (int i = 0; i < 4; i++) {
                whs[i] = __float2half_rn(wvv[p][i]);
                wls[i] = __float2half_rn(wvv[p][i] - __half2float(whs[i]));
            }
            *(uint2*)&wh[wcol[p] * 24 + wk4[p]] = *(uint2*)whs;
            *(uint2*)&wl[wcol[p] * 24 + wk4[p]] = *(uint2*)wls;
        }
        __syncthreads();

        if (kc + 1 < 16) {
            const int k0n = (kc + 1) * 16;
            #pragma unroll
            for (int p = 0; p < 2; p++) {
                xv[p] = *(const float4*)&x[(size_t)(rowBase + xrow[p]) * IN_DIM + k0n + xseg[p] * 4];
                #pragma unroll
                for (int i = 0; i < 4; i++)
                    wvv[p][i] = W[(size_t)(k0n + wk4[p] + i) * DMODEL + nBase + wcol[p]];
            }
        }

        uint32_t ah[4], al[4];
        ldsm4(ah, xh_b + aoff);
        ldsm4(al, xl_b + aoff);
        #pragma unroll
        for (int jp = 0; jp < 8; jp++) {
            uint32_t bh4[4], bl4[4];
            ldsm4(bh4, wh_b + boff[jp]);
            ldsm4(bl4, wl_b + boff[jp]);
            mma16816(oc[2*jp],     ah, bh4);
            mma16816(oc[2*jp + 1], ah, bh4 + 2);
            mma16816(oc[2*jp],     ah, bl4);
            mma16816(oc[2*jp + 1], ah, bl4 + 2);
            mma16816(oc[2*jp],     al, bh4);
            mma16816(oc[2*jp + 1], al, bh4 + 2);
        }
    }

    const int c2 = (lane & 3) * 2;

    if (z < 2) {
        __half* D = (z == 0) ? g_q16 : g_k16;
        const int row0 = rowBase + w * 16 + (lane >> 2);
        const int row1 = row0 + 8;
        const int b0_ = row0 / SEQ, s0 = row0 - b0_ * SEQ;
        const int b1_ = row1 / SEQ, s1 = row1 - b1_ * SEQ;
        #pragma unroll
        for (int j = 0; j < 16; j++) {
            int col = nBase + j * 8 + c2;
            int h = col >> 6, ch = col & 63;
            float bb0 = bias[col], bb1 = bias[col + 1];
            __half2 v0 = __floats2half2_rn(oc[j][0] + bb0, oc[j][1] + bb1);
            __half2 v1 = __floats2half2_rn(oc[j][2] + bb0, oc[j][3] + bb1);
            *(__half2*)&D[((size_t)(b0_ * NHEAD + h) * SEQ + s0) * HDIM + ch] = v0;
            *(__half2*)&D[((size_t)(b1_ * NHEAD + h) * SEQ + s1) * HDIM + ch] = v1;
        }
    } else {
        // V: ReLU + transpose via smem -> g_vt16[bh][d][s]
        __syncthreads();
        __half* T = (__half*)smraw;    // [128 rows][132 pitch] fp16
        const int r0l = w * 16 + (lane >> 2);
        const int r1l = r0l + 8;
        #pragma unroll
        for (int j = 0; j < 16; j++) {
            int col = j * 8 + c2;
            float bb0 = bias[nBase + col], bb1 = bias[nBase + col + 1];
            __half2 v0 = __floats2half2_rn(fmaxf(oc[j][0] + bb0, 0.f),
                                           fmaxf(oc[j][1] + bb1, 0.f));
            __half2 v1 = __floats2half2_rn(fmaxf(oc[j][2] + bb0, 0.f),
                                           fmaxf(oc[j][3] + bb1, 0.f));
            *(__half2*)&T[r0l * 132 + col] = v0;
            *(__half2*)&T[r1l * 132 + col] = v1;
        }
        __syncthreads();
        const int sl = lane * 4;
        const int grow = rowBase + sl;
        const int b_ = grow / SEQ, s_ = grow - b_ * SEQ;
        #pragma unroll
        for (int cj = 0; cj < 16; cj++) {
            int col = w * 16 + cj;
            int dcol = nBase + col;
            int h = dcol >> 6, ch = dcol & 63;
            __align__(8) __half v[4];
            #pragma unroll
            for (int i = 0; i < 4; i++) v[i] = T[(sl + i) * 132 + col];
            *(uint2*)&g_vt16[((size_t)(b_ * NHEAD + h) * HDIM + ch) * SEQ + s_] = *(uint2*)v;
        }
    }
}

// ---------------------------------------------------------------------------
// K2 fused: fp16 HMMA attention, two-phase. R12 structure (direct streaming
// p stores) but TWO 64-key tiles per __syncthreads with a 6-buffer cp.async
// ring (writer buffers (2i+2,2i+3)%6 vs straggler readers (2i-2,2i-1)%6 —
// distinct mod 6, so one sync per pair is safe). 13 syncs/phase vs 25.
// Dynamic smem: [0,48K) K ring (6x8K), [48K,96K) V ring (6x8K).
// ---------------------------------------------------------------------------
#define ATTN_SMEM_BYTES (2 * 6 * 8192)   // 98304

__global__ __launch_bounds__(256, 2) void attn_kernel(
    float* __restrict__ Pext, int use_ext, float* __restrict__ out)
{
    extern __shared__ __align__(16) char dsm[];

    float* P = use_ext ? Pext : g_scores_fallback;
    const int tid = threadIdx.x, w = tid >> 5, lane = tid & 31;
    const int bh = blockIdx.y;
    const int qBase = blockIdx.x * 128;

    const int row0 = qBase + w * 16 + (lane >> 2);
    const int row1 = row0 + 8;
    const int c2   = (lane & 3) * 2;
    const int lo0 = (row0 / NJOINT) * NJOINT, hi0 = lo0 + NJOINT;
    const int lo1 = (row1 / NJOINT) * NJOINT, hi1 = lo1 + NJOINT;
    const int wrow = qBase + w * 16;
    const int loW = (wrow / NJOINT) * NJOINT;
    const int hiW = ((wrow + 15) / NJOINT) * NJOINT + NJOINT;

    const __half* q = g_q16 + (size_t)bh * SEQ * HDIM;
    const char* kB = (const char*)(g_k16 + (size_t)bh * SEQ * HDIM);
    const char* vB = (const char*)(g_vt16 + (size_t)bh * HDIM * SEQ);

    uint32_t qf[4][4];
    {
        int r0c = min(row0, SEQ - 1), r1c = min(row1, SEQ - 1);
        #pragma unroll
        for (int t = 0; t < 4; t++) {
            qf[t][0] = *(const uint32_t*)&q[(size_t)r0c * HDIM + t*16 + c2];
            qf[t][1] = *(const uint32_t*)&q[(size_t)r1c * HDIM + t*16 + c2];
            qf[t][2] = *(const uint32_t*)&q[(size_t)r0c * HDIM + t*16 + 8 + c2];
            qf[t][3] = *(const uint32_t*)&q[(size_t)r1c * HDIM + t*16 + 8 + c2];
        }
    }

    const uint32_t sk_b = smem_u32(dsm);
    const uint32_t sv_b = sk_b + 49152;

    uint32_t dstoff[2]; uint32_t srcKoff[2], srcVoff[2];
    #pragma unroll
    for (int p = 0; p < 2; p++) {
        int i = tid + p * 256;
        int r = i >> 3, cb = (i & 7) * 16;
        dstoff[p]  = SW(r * 128 + cb);
        srcKoff[p] = r * 128 + cb;
        srcVoff[p] = r * (SEQ * 2) + cb;
    }
    const int lrow = lane & 7;
    const int lcb  = (lane >> 3) * 16;
    uint32_t lof[8];
    #pragma unroll
    for (int j = 0; j < 8; j++) lof[j] = SW((j * 8 + lrow) * 128 + lcb);

    float rsum0 = 0.f, rsum1 = 0.f;

    // ================= Phase A: rowsum only (pairs of tiles) =================
    #pragma unroll
    for (int p = 0; p < 2; p++) {
        cpasync16(sk_b + dstoff[p], kB + srcKoff[p]);                 // tile 0
        cpasync16(sk_b + 8192 + dstoff[p], kB + 8192 + srcKoff[p]);   // tile 1
    }
    cp_commit();

    uint32_t bA = sk_b;     // buffer base for current pair
    #pragma unroll 1
    for (int it = 0; it < 13; it++) {
        const int t0 = it * 2;
        if (it < 12) {
            uint32_t bN = bA + 16384; if (bN >= sk_b + 49152) bN -= 49152;
            #pragma unroll
            for (int p = 0; p < 2; p++)
                cpasync16(bN + dstoff[p], kB + (t0 + 2) * 8192 + srcKoff[p]);
            if (t0 + 3 < 25) {
                #pragma unroll
                for (int p = 0; p < 2; p++)
                    cpasync16(bN + 8192 + dstoff[p], kB + (t0 + 3) * 8192 + srcKoff[p]);
            }
            cp_commit();
            cp_wait1();
        } else cp_wait0();
        __syncthreads();

        #pragma unroll
        for (int sub = 0; sub < 2; sub++) {
            const int kt = t0 + sub;
            if (kt >= 25) break;
            const int k0 = kt * 64;
            const uint32_t cb_ = bA + sub * 8192;
            const bool needMask = (k0 < hiW) && (k0 + 64 > loW);

            #pragma unroll
            for (int jp = 0; jp < 4; jp++) {
                uint32_t b0[8], b1[8];
                {
                    uint32_t a = cb_ + lof[jp * 2];
                    ldsm4(b0, a); ldsm4(b0 + 4, a ^ 64);
                    uint32_t b = cb_ + lof[jp * 2 + 1];
                    ldsm4(b1, b); ldsm4(b1 + 4, b ^ 64);
                }
                float c0[4] = {0.f,0.f,0.f,0.f}, c1[4] = {0.f,0.f,0.f,0.f};
                #pragma unroll
                for (int t = 0; t < 4; t++) {
                    mma16816(c0, qf[t], b0 + 2*t);
                    mma16816(c1, qf[t], b1 + 2*t);
                }
                if (needMask) {
                    #pragma unroll
                    for (int jj = 0; jj < 2; jj++) {
                        const float* cc = jj ? c1 : c0;
                        int ka = k0 + (jp * 2 + jj) * 8 + c2, kb2 = ka + 1;
                        bool a00 = (ka  < lo0) | (ka  >= hi0) | (ka  == row0);
                        bool a01 = (kb2 < lo0) | (kb2 >= hi0) | (kb2 == row0);
                        bool a10 = (ka  < lo1) | (ka  >= hi1) | (ka  == row1);
                        bool a11 = (kb2 < lo1) | (kb2 >= hi1) | (kb2 == row1);
                        rsum0 += (a00 ? ex2f(cc[0] * EXPC) : 0.f)
                               + (a01 ? ex2f(cc[1] * EXPC) : 0.f);
                        rsum1 += (a10 ? ex2f(cc[2] * EXPC) : 0.f)
                               + (a11 ? ex2f(cc[3] * EXPC) : 0.f);
                    }
                } else {
                    rsum0 += ex2f(c0[0] * EXPC) + ex2f(c0[1] * EXPC)
                           + ex2f(c1[0] * EXPC) + ex2f(c1[1] * EXPC);
                    rsum1 += ex2f(c0[2] * EXPC) + ex2f(c0[3] * EXPC)
                           + ex2f(c1[2] * EXPC) + ex2f(c1[3] * EXPC);
                }
            }
        }
        bA += 16384; if (bA >= sk_b + 49152) bA -= 49152;
    }

    #pragma unroll
    for (int off = 1; off < 4; off <<= 1) {
        rsum0 += __shfl_xor_sync(0xffffffffu, rsum0, off);
        rsum1 += __shfl_xor_sync(0xffffffffu, rsum1, off);
    }
    const float inv0 = (row0 < SEQ) ? 1.f / rsum0 : 0.f;
    const float inv1 = (row1 < SEQ) ? 1.f / rsum1 : 0.f;

    float* prow0 = P + ((size_t)bh * SEQ + row0) * SEQ;
    float* prow1 = P + ((size_t)bh * SEQ + row1) * SEQ;

    float oc[8][4];
    #pragma unroll
    for (int j = 0; j < 8; j++) { oc[j][0]=0.f; oc[j][1]=0.f; oc[j][2]=0.f; oc[j][3]=0.f; }

    // phase-transition guard: stragglers of phase A still read K buffers
    __syncthreads();

    // ============ Phase B: recompute, write p, O += pV (pairs) ============
    #pragma unroll
    for (int p = 0; p < 2; p++) {
        cpasync16(sk_b + dstoff[p], kB + srcKoff[p]);
        cpasync16(sv_b + dstoff[p], vB + srcVoff[p]);
        cpasync16(sk_b + 8192 + dstoff[p], kB + 8192 + srcKoff[p]);
        cpasync16(sv_b + 8192 + dstoff[p], vB + 128 + srcVoff[p]);
    }
    cp_commit();

    bA = sk_b;
    #pragma unroll 1
    for (int it = 0; it < 13; it++) {
        const int t0 = it * 2;
        if (it < 12) {
            uint32_t bN = bA + 16384; if (bN >= sk_b + 49152) bN -= 49152;
            const uint32_t bNv = bN - sk_b + sv_b;
            #pragma unroll
            for (int p = 0; p < 2; p++) {
                cpasync16(bN + dstoff[p],  kB + (t0 + 2) * 8192 + srcKoff[p]);
                cpasync16(bNv + dstoff[p], vB + (t0 + 2) * 128  + srcVoff[p]);
            }
            if (t0 + 3 < 25) {
                #pragma unroll
                for (int p = 0; p < 2; p++) {
                    cpasync16(bN + 8192 + dstoff[p],  kB + (t0 + 3) * 8192 + srcKoff[p]);
                    cpasync16(bNv + 8192 + dstoff[p], vB + (t0 + 3) * 128  + srcVoff[p]);
                }
            }
            cp_commit();
            cp_wait1();
        } else cp_wait0();
        __syncthreads();

        #pragma unroll
        for (int sub = 0; sub < 2; sub++) {
            const int kt = t0 + sub;
            if (kt >= 25) break;
            const int k0 = kt * 64;
            const uint32_t ckb = bA + sub * 8192;
            const uint32_t cvb = ckb - sk_b + sv_b;
            const bool needMask = (k0 < hiW) && (k0 + 64 > loW);

            uint32_t pa[4][4];
            #pragma unroll
            for (int jp = 0; jp < 4; jp++) {
                uint32_t b0[8], b1[8];
                {
                    uint32_t a = ckb + lof[jp * 2];
                    ldsm4(b0, a); ldsm4(b0 + 4, a ^ 64);
                    uint32_t b = ckb + lof[jp * 2 + 1];
                    ldsm4(b1, b); ldsm4(b1 + 4, b ^ 64);
                }
                float c0[4] = {0.f,0.f,0.f,0.f}, c1[4] = {0.f,0.f,0.f,0.f};
                #pragma unroll
                for (int t = 0; t < 4; t++) {
                    mma16816(c0, qf[t], b0 + 2*t);
                    mma16816(c1, qf[t], b1 + 2*t);
                }
                if (needMask) {
                    #pragma unroll
                    for (int jj = 0; jj < 2; jj++) {
                        const float* cc = jj ? c1 : c0;
                        int ka = k0 + (jp * 2 + jj) * 8 + c2, kb2 = ka + 1;
                        bool a00 = (ka  < lo0) | (ka  >= hi0) | (ka  == row0);
                        bool a01 = (kb2 < lo0) | (kb2 >= hi0) | (kb2 == row0);
                        bool a10 = (ka  < lo1) | (ka  >= hi1) | (ka  == row1);
                        bool a11 = (kb2 < lo1) | (kb2 >= hi1) | (kb2 == row1);
                        float p00 = a00 ? ex2f(cc[0] * EXPC) * inv0 : 0.f;
                        float p01 = a01 ? ex2f(cc[1] * EXPC) * inv0 : 0.f;
                        float p10 = a10 ? ex2f(cc[2] * EXPC) * inv1 : 0.f;
                        float p11 = a11 ? ex2f(cc[3] * EXPC) * inv1 : 0.f;
                        if (row0 < SEQ) stg_cs2(&prow0[ka], p00, p01);
                        if (row1 < SEQ) stg_cs2(&prow1[ka], p10, p11);
                        __half2 h0 = __floats2half2_rn(p00, p01);
                        __half2 h1 = __floats2half2_rn(p10, p11);
                        pa[jp][jj * 2 + 0] = *(uint32_t*)&h0;
                        pa[jp][jj * 2 + 1] = *(uint32_t*)&h1;
                    }
                } else {
                    #pragma unroll
                    for (int jj = 0; jj < 2; jj++) {
                        const float* cc = jj ? c1 : c0;
                        int ka = k0 + (jp * 2 + jj) * 8 + c2;
                        float p00 = ex2f(cc[0] * EXPC) * inv0;
                        float p01 = ex2f(cc[1] * EXPC) * inv0;
                        float p10 = ex2f(cc[2] * EXPC) * inv1;
                        float p11 = ex2f(cc[3] * EXPC) * inv1;
                        if (row0 < SEQ) stg_cs2(&prow0[ka], p00, p01);
                        if (row1 < SEQ) stg_cs2(&prow1[ka], p10, p11);
                        __half2 h0 = __floats2half2_rn(p00, p01);
                        __half2 h1 = __floats2half2_rn(p10, p11);
                        pa[jp][jj * 2 + 0] = *(uint32_t*)&h0;
                        pa[jp][jj * 2 + 1] = *(uint32_t*)&h1;
                    }
                }
            }

            #pragma unroll
            for (int jp = 0; jp < 4; jp++) {
                uint32_t b0[8], b1[8];
                {
                    uint32_t a = cvb + lof[jp * 2];
                    ldsm4(b0, a); ldsm4(b0 + 4, a ^ 64);
                    uint32_t b = cvb + lof[jp * 2 + 1];
                    ldsm4(b1, b); ldsm4(b1 + 4, b ^ 64);
                }
                #pragma unroll
                for (int t = 0; t < 4; t++) {
                    mma16816(oc[jp * 2],     pa[t], b0 + 2*t);
                    mma16816(oc[jp * 2 + 1], pa[t], b1 + 2*t);
                }
            }
        }
        bA += 16384; if (bA >= sk_b + 49152) bA -= 49152;
    }

    const int b_ = bh >> 3, h_ = bh & 7;
    float* ob0 = out + ((size_t)b_ * SEQ + row0) * DMODEL + h_ * HDIM;
    float* ob1 = out + ((size_t)b_ * SEQ + row1) * DMODEL + h_ * HDIM;
    #pragma unroll
    for (int j = 0; j < 8; j++) {
        if (row0 < SEQ) *(float2*)&ob0[j * 8 + c2] = make_float2(oc[j][0], oc[j][1]);
        if (row1 < SEQ) *(float2*)&ob1[j * 8 + c2] = make_float2(oc[j][2], oc[j][3]);
    }
}

// ---------------------------------------------------------------------------
extern "C" void kernel_launch(void* const* d_in, const int* in_sizes, int n_in,
                              void* d_out, int out_size)
{
    const float* x  = (const float*)d_in[0];
    const float* wq = (const float*)d_in[1];
    const float* bq = (const float*)d_in[2];
    const float* wk = (const float*)d_in[3];
    const float* bk = (const float*)d_in[4];
    const float* wv = (const float*)d_in[5];
    const float* bv = (const float*)d_in[6];
    float* out = (float*)d_out;

    int use_ext = ((size_t)out_size >= OUT_ELEMS + PATT_ELEMS) ? 1 : 0;
    float* Pext = out + OUT_ELEMS;

    static int attr_set = 0;
    if (!attr_set) {
        cudaFuncSetAttribute(attn_kernel, cudaFuncAttributeMaxDynamicSharedMemorySize,
                             ATTN_SMEM_BYTES);
        attr_set = 1;
    }

    {   // K1: QKV -> fp16, all HMMA (V transposed via smem)
        dim3 grid(DMODEL / 128, (BATCH * SEQ) / 128, 3);
        qkv_kernel<<<grid, 256>>>(x, wq, bq, wk, bk, wv, bv);
    }
    {   // K2 fused: two-phase fp16 HMMA attention -> p (final) + out
        dim3 grid((SEQ + 127) / 128, BH);
        attn_kernel<<<grid, 256, ATTN_SMEM_BYTES>>>(Pext, use_ext, out);
    }
}